// round 13
// baseline (speedup 1.0000x reference)
#include <cuda_runtime.h>
#include <cuda_fp16.h>

#define MAXN 100000
#define MAXE 1600000
#define MAXTOT (MAXN + MAXE)
#define NEG_SLOPE 0.2f

// ---------------- scratch ---------------------------------------------------
__device__ __align__(16) __half2 g_h1h[MAXN * 64];   // layer-1 features, fp16
__device__ __align__(16) float g_als1[MAXN * 4];
__device__ __align__(16) float g_ald1[MAXN * 4];
__device__ __align__(16) float g_x2[MAXN * 128];
__device__ __align__(16) __half g_h2h[MAXN * 16];    // layer-2 features, fp16
__device__ float g_als2[MAXN];
__device__ float g_ald2[MAXN];
__device__ int g_deg[MAXN];
__device__ int g_rowptr[MAXN];
__device__ int g_cursor[MAXN];
__device__ int g_col[MAXTOT];
__device__ int g_src[MAXE];
__device__ int g_dst[MAXE];
__device__ int g_is64;
__device__ int g_total;

// ---------------- f32x2 helpers ---------------------------------------------
__device__ __forceinline__ unsigned long long pack2(float a, float b) {
    unsigned long long r;
    asm("mov.b64 %0, {%1, %2};" : "=l"(r) : "f"(a), "f"(b));
    return r;
}
__device__ __forceinline__ void fma2(unsigned long long& d, unsigned long long a,
                                     unsigned long long b) {
    asm("fma.rn.f32x2 %0, %1, %2, %0;" : "+l"(d) : "l"(a), "l"(b));
}
__device__ __forceinline__ float2 unpack2(unsigned long long v) {
    float2 f;
    asm("mov.b64 {%0, %1}, %2;" : "=f"(f.x), "=f"(f.y) : "l"(v));
    return f;
}

__device__ __forceinline__ float leaky(float e) { return e > 0.f ? e : NEG_SLOPE * e; }

// ---------------- edge-index probe / normalize / count -----------------------
__global__ void k_probe(const int* __restrict__ ei32, int E) {
    if (threadIdx.x == 0 && blockIdx.x == 0) {
        int cnt = E < 64 ? E : 64;
        int zeros = 0;
        for (int i = 0; i < cnt; i++) zeros += (ei32[2 * i + 1] == 0) ? 1 : 0;
        g_is64 = (zeros == cnt) ? 1 : 0;
        g_total = 0;
    }
}

__global__ void k_zero_deg(int n) {
    int i = blockIdx.x * blockDim.x + threadIdx.x;
    if (i < n) g_deg[i] = 0;
}

__global__ void k_convert(const void* __restrict__ ei, int E, int N) {
    int e = blockIdx.x * blockDim.x + threadIdx.x;
    if (e >= E) return;
    int s, d;
    if (g_is64) {
        const long long* p = (const long long*)ei;
        s = (int)p[e];
        d = (int)p[E + e];
    } else {
        const int* p = (const int*)ei;
        s = p[e];
        d = p[E + e];
    }
    s = min(max(s, 0), N - 1);
    d = min(max(d, 0), N - 1);
    g_src[e] = s;
    g_dst[e] = d;
    atomicAdd(&g_deg[d], 1);
}

// parallel segment allocator (order-free CSR)
__global__ void k_alloc(int n) {
    int i = blockIdx.x * blockDim.x + threadIdx.x;
    int lane = threadIdx.x & 31;
    int v = (i < n) ? g_deg[i] + 1 : 0;
    int incl = v;
#pragma unroll
    for (int off = 1; off < 32; off <<= 1) {
        int t = __shfl_up_sync(0xFFFFFFFFu, incl, off);
        if (lane >= off) incl += t;
    }
    int tot = __shfl_sync(0xFFFFFFFFu, incl, 31);
    int base = 0;
    if (lane == 0) base = atomicAdd(&g_total, tot);
    base = __shfl_sync(0xFFFFFFFFu, base, 0);
    int pos = base + incl - v;
    if (i < n) {
        g_rowptr[i] = pos;
        g_col[pos] = i;
        g_cursor[i] = pos + 1;
    }
}

__global__ void k_fill(int E) {
    int e = blockIdx.x * blockDim.x + threadIdx.x;
    if (e < E) {
        int pos = atomicAdd(&g_cursor[g_dst[e]], 1);
        g_col[pos] = g_src[e];
    }
}

// ---------------- GEMM1: 128x128 tile, 8x8 register blocking, fp16 h1 out ----
__global__ void k_gemm1(const float* __restrict__ x, const float* __restrict__ W,
                        const float* __restrict__ asrc, const float* __restrict__ adst,
                        int n) {
    __shared__ float xs[128 * 33];
    __shared__ float ws[32 * 128];
    int t = threadIdx.x;
    int tx = t & 15, ty = t >> 4;
    int row0 = blockIdx.x * 128;

    unsigned long long acc[8][4];
#pragma unroll
    for (int i = 0; i < 8; i++)
#pragma unroll
        for (int j = 0; j < 4; j++) acc[i][j] = pack2(0.f, 0.f);

    for (int kc = 0; kc < 128; kc += 32) {
        for (int i = t; i < 1024; i += 256) {
            int r = i >> 3, cq = i & 7;
            float4 v = make_float4(0.f, 0.f, 0.f, 0.f);
            if (row0 + r < n)
                v = *(const float4*)&x[(size_t)(row0 + r) * 128 + kc + cq * 4];
            float* p = &xs[r * 33 + cq * 4];
            p[0] = v.x; p[1] = v.y; p[2] = v.z; p[3] = v.w;
        }
        for (int i = t; i < 1024; i += 256)
            *(float4*)&ws[i * 4] = *(const float4*)&W[(size_t)kc * 128 + i * 4];
        __syncthreads();
#pragma unroll 4
        for (int k = 0; k < 32; k++) {
            float4 wa = *(const float4*)&ws[k * 128 + tx * 8];
            float4 wb = *(const float4*)&ws[k * 128 + tx * 8 + 4];
            unsigned long long wp0 = pack2(wa.x, wa.y);
            unsigned long long wp1 = pack2(wa.z, wa.w);
            unsigned long long wp2 = pack2(wb.x, wb.y);
            unsigned long long wp3 = pack2(wb.z, wb.w);
#pragma unroll
            for (int i = 0; i < 8; i++) {
                float xv = xs[(ty * 8 + i) * 33 + k];
                unsigned long long xp = pack2(xv, xv);
                fma2(acc[i][0], xp, wp0);
                fma2(acc[i][1], xp, wp1);
                fma2(acc[i][2], xp, wp2);
                fma2(acc[i][3], xp, wp3);
            }
        }
        __syncthreads();
    }

    int h0 = tx >> 2;
    int base = (tx & 3) * 8;
    float aS[8], aD[8];
#pragma unroll
    for (int j = 0; j < 8; j++) {
        aS[j] = asrc[h0 * 32 + base + j];
        aD[j] = adst[h0 * 32 + base + j];
    }
#pragma unroll
    for (int i = 0; i < 8; i++) {
        int row = row0 + ty * 8 + i;
        float2 p0 = unpack2(acc[i][0]);
        float2 p1 = unpack2(acc[i][1]);
        float2 p2 = unpack2(acc[i][2]);
        float2 p3 = unpack2(acc[i][3]);
        float hv[8] = {p0.x, p0.y, p1.x, p1.y, p2.x, p2.y, p3.x, p3.y};
        if (row < n) {
            __half2 hh[4];
            hh[0] = __floats2half2_rn(hv[0], hv[1]);
            hh[1] = __floats2half2_rn(hv[2], hv[3]);
            hh[2] = __floats2half2_rn(hv[4], hv[5]);
            hh[3] = __floats2half2_rn(hv[6], hv[7]);
            *(float4*)&g_h1h[(size_t)row * 64 + tx * 4] = *(float4*)hh;
        }
        float pS = 0.f, pD = 0.f;
#pragma unroll
        for (int j = 0; j < 8; j++) {
            pS = fmaf(hv[j], aS[j], pS);
            pD = fmaf(hv[j], aD[j], pD);
        }
        pS += __shfl_xor_sync(0xFFFFFFFFu, pS, 1);
        pD += __shfl_xor_sync(0xFFFFFFFFu, pD, 1);
        pS += __shfl_xor_sync(0xFFFFFFFFu, pS, 2);
        pD += __shfl_xor_sync(0xFFFFFFFFu, pD, 2);
        if ((tx & 3) == 0 && row < n) {
            g_als1[row * 4 + h0] = pS;
            g_ald1[row * 4 + h0] = pD;
        }
    }
}

// ---------------- Layer-1 aggregation: pipelined single-pass, fp16 gather ----
// Padded lanes carry ex=0 -> contribute nothing; their gathers hit row 0 (hot).
__global__ void k_agg1(const float* __restrict__ b1, int n) {
    int w = (blockIdx.x * blockDim.x + threadIdx.x) >> 5;
    int lane = threadIdx.x & 31;
    if (w >= n) return;
    int start = g_rowptr[w];
    int end = start + g_deg[w] + 1;
    float4 aldv = *(const float4*)&g_ald1[w * 4];
    int hd = lane & 3;
    float aldd = (hd == 0) ? aldv.x : (hd == 1) ? aldv.y : (hd == 2) ? aldv.z : aldv.w;
    int hg = lane >> 3;
    int c = lane << 2;

    float den = 0.f;
    float a0 = 0.f, a1 = 0.f, a2 = 0.f, a3 = 0.f;

    // pipeline: front of batch 0
    int j = start + (lane >> 2);
    int scol = 0; float als = 0.f;
    bool valid = (j < end);
    if (valid) { scol = g_col[j]; als = g_als1[scol * 4 + hd]; }

    for (int jb = start; jb < end; jb += 8) {
        float ex = valid ? __expf(leaky(als + aldd)) : 0.f;
        den += ex;
        // prefetch next batch front (overlaps with the gather below)
        int jn = jb + 8 + (lane >> 2);
        int nscol = 0; float nals = 0.f;
        bool nvalid = (jn < end);
        if (nvalid) { nscol = g_col[jn]; nals = g_als1[nscol * 4 + hd]; }
        // branch-free gather of 8 edge slots
#pragma unroll
        for (int u = 0; u < 8; u++) {
            int s = __shfl_sync(0xFFFFFFFFu, scol, u * 4);
            float a = __shfl_sync(0xFFFFFFFFu, ex, u * 4 + hg);
            uint2 raw = *(const uint2*)&g_h1h[(size_t)s * 64 + lane * 2];
            float2 f0 = __half22float2(*(__half2*)&raw.x);
            float2 f1 = __half22float2(*(__half2*)&raw.y);
            a0 = fmaf(f0.x, a, a0);
            a1 = fmaf(f0.y, a, a1);
            a2 = fmaf(f1.x, a, a2);
            a3 = fmaf(f1.y, a, a3);
        }
        scol = nscol; als = nals; valid = nvalid;
    }
    den += __shfl_xor_sync(0xFFFFFFFFu, den, 4);
    den += __shfl_xor_sync(0xFFFFFFFFu, den, 8);
    den += __shfl_xor_sync(0xFFFFFFFFu, den, 16);
    float rd = 1.0f / den;
    float rdg = __shfl_sync(0xFFFFFFFFu, rd, hg);
    float4 bb = *(const float4*)&b1[c];
    float4 o;
    o.x = fmaxf(fmaf(a0, rdg, bb.x), 0.f);
    o.y = fmaxf(fmaf(a1, rdg, bb.y), 0.f);
    o.z = fmaxf(fmaf(a2, rdg, bb.z), 0.f);
    o.w = fmaxf(fmaf(a3, rdg, bb.w), 0.f);
    *(float4*)&g_x2[(size_t)w * 128 + c] = o;
}

// ---------------- GEMM2: h2 = x2 @ W2 [128,16] (fp16 out) + fused dots -------
__global__ void k_gemm2(const float* __restrict__ W, const float* __restrict__ asrc,
                        const float* __restrict__ adst, int n) {
    __shared__ float xs[16 * 128];
    __shared__ float ws[128 * 16];
    int t = threadIdx.x;
    int r0 = blockIdx.x * 16;
    for (int i = t; i < 128 * 16 / 4; i += 256)
        *(float4*)&ws[i * 4] = *(const float4*)&W[i * 4];
    for (int i = t; i < 16 * 128 / 4; i += 256) {
        int r = (i * 4) >> 7;
        float4 v = make_float4(0.f, 0.f, 0.f, 0.f);
        if (r0 + r < n) v = *(const float4*)&g_x2[(size_t)r0 * 128 + i * 4];
        *(float4*)&xs[i * 4] = v;
    }
    __syncthreads();
    int row = t >> 4, c = t & 15;
    float acc = 0.f;
#pragma unroll 8
    for (int k = 0; k < 128; k++) acc = fmaf(xs[row * 128 + k], ws[k * 16 + c], acc);
    int grow = r0 + row;
    if (grow < n) g_h2h[grow * 16 + c] = __float2half_rn(acc);
    float pS = acc * asrc[c];
    float pD = acc * adst[c];
#pragma unroll
    for (int step = 1; step < 16; step <<= 1) {
        pS += __shfl_xor_sync(0xFFFFFFFFu, pS, step);
        pD += __shfl_xor_sync(0xFFFFFFFFu, pD, step);
    }
    if (c == 0 && grow < n) {
        g_als2[grow] = pS;
        g_ald2[grow] = pD;
    }
}

// ---------------- Layer-2 aggregation: single-pass, fp16, MLP-8 gather -------
// Layout: 4 edges x 8 lanes; each lane owns one half2 (2 cols) of h2.
__global__ void k_agg2(const float* __restrict__ b2, float* __restrict__ out, int n) {
    int w = (blockIdx.x * blockDim.x + threadIdx.x) >> 5;
    int lane = threadIdx.x & 31;
    if (w >= n) return;
    int start = g_rowptr[w];
    int end = start + g_deg[w] + 1;
    float ald = g_ald2[w];
    int p = lane & 7;        // col pair index: cols 2p, 2p+1
    int eg = lane >> 3;      // edge subgroup 0..3

    float den = 0.f, acc0 = 0.f, acc1 = 0.f;
    for (int jb = start; jb < end; jb += 32) {
        int j = jb + lane;
        int scol = 0;
        float ex = 0.f;
        if (j < end) {
            scol = g_col[j];
            ex = __expf(leaky(g_als2[scol] + ald));
            den += ex;
        }
        // branch-free: pad slots have ex=0 (scol=0 hot row)
#pragma unroll
        for (int v = 0; v < 8; v++) {
            int su = v * 4 + eg;
            int s = __shfl_sync(0xFFFFFFFFu, scol, su);
            float a = __shfl_sync(0xFFFFFFFFu, ex, su);
            __half2 hh = *(const __half2*)&g_h2h[s * 16 + p * 2];
            float2 f = __half22float2(hh);
            acc0 = fmaf(f.x, a, acc0);
            acc1 = fmaf(f.y, a, acc1);
        }
    }
#pragma unroll
    for (int off = 16; off; off >>= 1) den += __shfl_xor_sync(0xFFFFFFFFu, den, off);
    float rd = 1.0f / den;
    // reduce over edge subgroups (lane bits 3,4)
    acc0 += __shfl_xor_sync(0xFFFFFFFFu, acc0, 8);
    acc1 += __shfl_xor_sync(0xFFFFFFFFu, acc1, 8);
    acc0 += __shfl_xor_sync(0xFFFFFFFFu, acc0, 16);
    acc1 += __shfl_xor_sync(0xFFFFFFFFu, acc1, 16);
    if (lane < 8) {
        float2 o = make_float2(fmaf(acc0, rd, b2[2 * p]),
                               fmaf(acc1, rd, b2[2 * p + 1]));
        *(float2*)&out[(size_t)w * 16 + 2 * p] = o;
    }
}

// ---------------- launch -----------------------------------------------------
extern "C" void kernel_launch(void* const* d_in, const int* in_sizes, int n_in,
                              void* d_out, int out_size) {
    const float* x = (const float*)d_in[0];
    const void* ei = d_in[1];
    const float* W1 = (const float*)d_in[2];
    const float* as1 = (const float*)d_in[3];
    const float* ad1 = (const float*)d_in[4];
    const float* b1 = (const float*)d_in[5];
    const float* W2 = (const float*)d_in[6];
    const float* as2 = (const float*)d_in[7];
    const float* ad2 = (const float*)d_in[8];
    const float* b2 = (const float*)d_in[9];
    float* out = (float*)d_out;

    int N = in_sizes[0] / 128;
    int E = in_sizes[1] / 2;
    if (N > MAXN) N = MAXN;
    if (E > MAXE) E = MAXE;

    static cudaStream_t s2 = nullptr;
    static cudaEvent_t evRoot = nullptr, evG1 = nullptr;
    if (s2 == nullptr) {
        cudaStreamCreateWithFlags(&s2, cudaStreamNonBlocking);
        cudaEventCreateWithFlags(&evRoot, cudaEventDisableTiming);
        cudaEventCreateWithFlags(&evG1, cudaEventDisableTiming);
    }

    // branch: GEMM1 runs parallel to the CSR build
    cudaEventRecord(evRoot, 0);
    cudaStreamWaitEvent(s2, evRoot, 0);
    k_gemm1<<<(N + 127) / 128, 256, 0, s2>>>(x, W1, as1, ad1, N);
    cudaEventRecord(evG1, s2);

    k_probe<<<1, 32>>>((const int*)ei, E);
    k_zero_deg<<<(N + 255) / 256, 256>>>(N);
    k_convert<<<(E + 255) / 256, 256>>>(ei, E, N);
    k_alloc<<<(N + 255) / 256, 256>>>(N);
    k_fill<<<(E + 255) / 256, 256>>>(E);

    cudaStreamWaitEvent(0, evG1, 0);
    k_agg1<<<(N + 7) / 8, 256>>>(b1, N);
    k_gemm2<<<(N + 15) / 16, 256>>>(W2, as2, ad2, N);
    k_agg2<<<(N + 7) / 8, 256>>>(b2, out, N);
}

// round 14
// speedup vs baseline: 1.5260x; 1.5260x over previous
#include <cuda_runtime.h>
#include <cuda_fp16.h>

#define MAXN 100000
#define MAXE 1600000
#define MAXTOT (MAXN + MAXE)
#define NEG_SLOPE 0.2f

// ---------------- scratch ---------------------------------------------------
__device__ __align__(16) __half2 g_h1h[MAXN * 64];   // layer-1 features, fp16
__device__ __align__(16) float g_als1[MAXN * 4];
__device__ __align__(16) float g_ald1[MAXN * 4];
__device__ __align__(16) float g_x2[MAXN * 128];
__device__ __align__(16) __half g_h2h[MAXN * 16];    // layer-2 features, fp16
__device__ float g_als2[MAXN];
__device__ float g_ald2[MAXN];
__device__ int g_deg[MAXN];
__device__ int g_rowptr[MAXN];
__device__ int g_cursor[MAXN];
__device__ int g_col[MAXTOT];
__device__ int g_src[MAXE];
__device__ int g_dst[MAXE];
__device__ int g_is64;
__device__ int g_total;

// ---------------- f32x2 helpers ---------------------------------------------
__device__ __forceinline__ unsigned long long pack2(float a, float b) {
    unsigned long long r;
    asm("mov.b64 %0, {%1, %2};" : "=l"(r) : "f"(a), "f"(b));
    return r;
}
__device__ __forceinline__ void fma2(unsigned long long& d, unsigned long long a,
                                     unsigned long long b) {
    asm("fma.rn.f32x2 %0, %1, %2, %0;" : "+l"(d) : "l"(a), "l"(b));
}
__device__ __forceinline__ float2 unpack2(unsigned long long v) {
    float2 f;
    asm("mov.b64 {%0, %1}, %2;" : "=f"(f.x), "=f"(f.y) : "l"(v));
    return f;
}

__device__ __forceinline__ float leaky(float e) { return e > 0.f ? e : NEG_SLOPE * e; }

// ---------------- edge-index probe / normalize / count -----------------------
__global__ void k_probe(const int* __restrict__ ei32, int E) {
    if (threadIdx.x == 0 && blockIdx.x == 0) {
        int cnt = E < 64 ? E : 64;
        int zeros = 0;
        for (int i = 0; i < cnt; i++) zeros += (ei32[2 * i + 1] == 0) ? 1 : 0;
        g_is64 = (zeros == cnt) ? 1 : 0;
        g_total = 0;
    }
}

__global__ void k_zero_deg(int n) {
    int i = blockIdx.x * blockDim.x + threadIdx.x;
    if (i < n) g_deg[i] = 0;
}

__global__ void k_convert(const void* __restrict__ ei, int E, int N) {
    int e = blockIdx.x * blockDim.x + threadIdx.x;
    if (e >= E) return;
    int s, d;
    if (g_is64) {
        const long long* p = (const long long*)ei;
        s = (int)p[e];
        d = (int)p[E + e];
    } else {
        const int* p = (const int*)ei;
        s = p[e];
        d = p[E + e];
    }
    s = min(max(s, 0), N - 1);
    d = min(max(d, 0), N - 1);
    g_src[e] = s;
    g_dst[e] = d;
    atomicAdd(&g_deg[d], 1);
}

// parallel segment allocator (order-free CSR)
__global__ void k_alloc(int n) {
    int i = blockIdx.x * blockDim.x + threadIdx.x;
    int lane = threadIdx.x & 31;
    int v = (i < n) ? g_deg[i] + 1 : 0;
    int incl = v;
#pragma unroll
    for (int off = 1; off < 32; off <<= 1) {
        int t = __shfl_up_sync(0xFFFFFFFFu, incl, off);
        if (lane >= off) incl += t;
    }
    int tot = __shfl_sync(0xFFFFFFFFu, incl, 31);
    int base = 0;
    if (lane == 0) base = atomicAdd(&g_total, tot);
    base = __shfl_sync(0xFFFFFFFFu, base, 0);
    int pos = base + incl - v;
    if (i < n) {
        g_rowptr[i] = pos;
        g_col[pos] = i;
        g_cursor[i] = pos + 1;
    }
}

__global__ void k_fill(int E) {
    int e = blockIdx.x * blockDim.x + threadIdx.x;
    if (e < E) {
        int pos = atomicAdd(&g_cursor[g_dst[e]], 1);
        g_col[pos] = g_src[e];
    }
}

// ---------------- GEMM1: 128x128 tile, 8x8 register blocking, fp16 h1 out ----
__global__ void k_gemm1(const float* __restrict__ x, const float* __restrict__ W,
                        const float* __restrict__ asrc, const float* __restrict__ adst,
                        int n) {
    __shared__ float xs[128 * 33];
    __shared__ float ws[32 * 128];
    int t = threadIdx.x;
    int tx = t & 15, ty = t >> 4;
    int row0 = blockIdx.x * 128;

    unsigned long long acc[8][4];
#pragma unroll
    for (int i = 0; i < 8; i++)
#pragma unroll
        for (int j = 0; j < 4; j++) acc[i][j] = pack2(0.f, 0.f);

    for (int kc = 0; kc < 128; kc += 32) {
        for (int i = t; i < 1024; i += 256) {
            int r = i >> 3, cq = i & 7;
            float4 v = make_float4(0.f, 0.f, 0.f, 0.f);
            if (row0 + r < n)
                v = *(const float4*)&x[(size_t)(row0 + r) * 128 + kc + cq * 4];
            float* p = &xs[r * 33 + cq * 4];
            p[0] = v.x; p[1] = v.y; p[2] = v.z; p[3] = v.w;
        }
        for (int i = t; i < 1024; i += 256)
            *(float4*)&ws[i * 4] = *(const float4*)&W[(size_t)kc * 128 + i * 4];
        __syncthreads();
#pragma unroll 4
        for (int k = 0; k < 32; k++) {
            float4 wa = *(const float4*)&ws[k * 128 + tx * 8];
            float4 wb = *(const float4*)&ws[k * 128 + tx * 8 + 4];
            unsigned long long wp0 = pack2(wa.x, wa.y);
            unsigned long long wp1 = pack2(wa.z, wa.w);
            unsigned long long wp2 = pack2(wb.x, wb.y);
            unsigned long long wp3 = pack2(wb.z, wb.w);
#pragma unroll
            for (int i = 0; i < 8; i++) {
                float xv = xs[(ty * 8 + i) * 33 + k];
                unsigned long long xp = pack2(xv, xv);
                fma2(acc[i][0], xp, wp0);
                fma2(acc[i][1], xp, wp1);
                fma2(acc[i][2], xp, wp2);
                fma2(acc[i][3], xp, wp3);
            }
        }
        __syncthreads();
    }

    int h0 = tx >> 2;
    int base = (tx & 3) * 8;
    float aS[8], aD[8];
#pragma unroll
    for (int j = 0; j < 8; j++) {
        aS[j] = asrc[h0 * 32 + base + j];
        aD[j] = adst[h0 * 32 + base + j];
    }
#pragma unroll
    for (int i = 0; i < 8; i++) {
        int row = row0 + ty * 8 + i;
        float2 p0 = unpack2(acc[i][0]);
        float2 p1 = unpack2(acc[i][1]);
        float2 p2 = unpack2(acc[i][2]);
        float2 p3 = unpack2(acc[i][3]);
        float hv[8] = {p0.x, p0.y, p1.x, p1.y, p2.x, p2.y, p3.x, p3.y};
        if (row < n) {
            __half2 hh[4];
            hh[0] = __floats2half2_rn(hv[0], hv[1]);
            hh[1] = __floats2half2_rn(hv[2], hv[3]);
            hh[2] = __floats2half2_rn(hv[4], hv[5]);
            hh[3] = __floats2half2_rn(hv[6], hv[7]);
            *(float4*)&g_h1h[(size_t)row * 64 + tx * 4] = *(float4*)hh;
        }
        float pS = 0.f, pD = 0.f;
#pragma unroll
        for (int j = 0; j < 8; j++) {
            pS = fmaf(hv[j], aS[j], pS);
            pD = fmaf(hv[j], aD[j], pD);
        }
        pS += __shfl_xor_sync(0xFFFFFFFFu, pS, 1);
        pD += __shfl_xor_sync(0xFFFFFFFFu, pD, 1);
        pS += __shfl_xor_sync(0xFFFFFFFFu, pS, 2);
        pD += __shfl_xor_sync(0xFFFFFFFFu, pD, 2);
        if ((tx & 3) == 0 && row < n) {
            g_als1[row * 4 + h0] = pS;
            g_ald1[row * 4 + h0] = pD;
        }
    }
}

// ---------------- Layer-1 aggregation: single-pass, fp16, front-prefetched ---
// cnt-bounded gather (R12 traffic) + prefetch of the next batch's front chain.
__global__ void k_agg1(const float* __restrict__ b1, int n) {
    int w = (blockIdx.x * blockDim.x + threadIdx.x) >> 5;
    int lane = threadIdx.x & 31;
    if (w >= n) return;
    int start = g_rowptr[w];
    int end = start + g_deg[w] + 1;
    float4 aldv = *(const float4*)&g_ald1[w * 4];
    int hd = lane & 3;
    float aldd = (hd == 0) ? aldv.x : (hd == 1) ? aldv.y : (hd == 2) ? aldv.z : aldv.w;
    int hg = lane >> 3;
    int c = lane << 2;

    float den = 0.f;
    float a0 = 0.f, a1 = 0.f, a2 = 0.f, a3 = 0.f;

    // front of batch 0
    int j = start + (lane >> 2);
    int scol = 0; float als = 0.f;
    bool valid = (j < end);
    if (valid) { scol = g_col[j]; als = g_als1[scol * 4 + hd]; }

    for (int jb = start; jb < end; jb += 8) {
        float ex = valid ? __expf(leaky(als + aldd)) : 0.f;
        den += ex;
        // prefetch next batch's front (overlaps with this batch's gather)
        int jn = jb + 8 + (lane >> 2);
        int nscol = 0; float nals = 0.f;
        bool nvalid = (jn < end);
        if (nvalid) { nscol = g_col[jn]; nals = g_als1[nscol * 4 + hd]; }

        int cnt = min(8, end - jb);
        if (cnt == 8) {
#pragma unroll
            for (int u = 0; u < 8; u++) {
                int s = __shfl_sync(0xFFFFFFFFu, scol, u * 4);
                float a = __shfl_sync(0xFFFFFFFFu, ex, u * 4 + hg);
                uint2 raw = *(const uint2*)&g_h1h[(size_t)s * 64 + lane * 2];
                float2 f0 = __half22float2(*(__half2*)&raw.x);
                float2 f1 = __half22float2(*(__half2*)&raw.y);
                a0 = fmaf(f0.x, a, a0);
                a1 = fmaf(f0.y, a, a1);
                a2 = fmaf(f1.x, a, a2);
                a3 = fmaf(f1.y, a, a3);
            }
        } else {
            for (int u = 0; u < cnt; u++) {
                int s = __shfl_sync(0xFFFFFFFFu, scol, u * 4);
                float a = __shfl_sync(0xFFFFFFFFu, ex, u * 4 + hg);
                uint2 raw = *(const uint2*)&g_h1h[(size_t)s * 64 + lane * 2];
                float2 f0 = __half22float2(*(__half2*)&raw.x);
                float2 f1 = __half22float2(*(__half2*)&raw.y);
                a0 = fmaf(f0.x, a, a0);
                a1 = fmaf(f0.y, a, a1);
                a2 = fmaf(f1.x, a, a2);
                a3 = fmaf(f1.y, a, a3);
            }
        }
        scol = nscol; als = nals; valid = nvalid;
    }
    den += __shfl_xor_sync(0xFFFFFFFFu, den, 4);
    den += __shfl_xor_sync(0xFFFFFFFFu, den, 8);
    den += __shfl_xor_sync(0xFFFFFFFFu, den, 16);
    float rd = 1.0f / den;
    float rdg = __shfl_sync(0xFFFFFFFFu, rd, hg);
    float4 bb = *(const float4*)&b1[c];
    float4 o;
    o.x = fmaxf(fmaf(a0, rdg, bb.x), 0.f);
    o.y = fmaxf(fmaf(a1, rdg, bb.y), 0.f);
    o.z = fmaxf(fmaf(a2, rdg, bb.z), 0.f);
    o.w = fmaxf(fmaf(a3, rdg, bb.w), 0.f);
    *(float4*)&g_x2[(size_t)w * 128 + c] = o;
}

// ---------------- GEMM2: h2 = x2 @ W2 [128,16] (fp16 out) + fused dots -------
__global__ void k_gemm2(const float* __restrict__ W, const float* __restrict__ asrc,
                        const float* __restrict__ adst, int n) {
    __shared__ float xs[16 * 128];
    __shared__ float ws[128 * 16];
    int t = threadIdx.x;
    int r0 = blockIdx.x * 16;
    for (int i = t; i < 128 * 16 / 4; i += 256)
        *(float4*)&ws[i * 4] = *(const float4*)&W[i * 4];
    for (int i = t; i < 16 * 128 / 4; i += 256) {
        int r = (i * 4) >> 7;
        float4 v = make_float4(0.f, 0.f, 0.f, 0.f);
        if (r0 + r < n) v = *(const float4*)&g_x2[(size_t)r0 * 128 + i * 4];
        *(float4*)&xs[i * 4] = v;
    }
    __syncthreads();
    int row = t >> 4, c = t & 15;
    float acc = 0.f;
#pragma unroll 8
    for (int k = 0; k < 128; k++) acc = fmaf(xs[row * 128 + k], ws[k * 16 + c], acc);
    int grow = r0 + row;
    if (grow < n) g_h2h[grow * 16 + c] = __float2half_rn(acc);
    float pS = acc * asrc[c];
    float pD = acc * adst[c];
#pragma unroll
    for (int step = 1; step < 16; step <<= 1) {
        pS += __shfl_xor_sync(0xFFFFFFFFu, pS, step);
        pD += __shfl_xor_sync(0xFFFFFFFFu, pD, step);
    }
    if (c == 0 && grow < n) {
        g_als2[grow] = pS;
        g_ald2[grow] = pD;
    }
}

// ---------------- Layer-2 aggregation: single-pass, fp16, bounded MLP-4 ------
// 4 edges x 8 lanes per iteration; ceil(cnt/4) iterations (<=3 wasted slots,
// inert because their ex=0).
__global__ void k_agg2(const float* __restrict__ b2, float* __restrict__ out, int n) {
    int w = (blockIdx.x * blockDim.x + threadIdx.x) >> 5;
    int lane = threadIdx.x & 31;
    if (w >= n) return;
    int start = g_rowptr[w];
    int end = start + g_deg[w] + 1;
    float ald = g_ald2[w];
    int p = lane & 7;        // col pair index: cols 2p, 2p+1
    int eg = lane >> 3;      // edge subgroup 0..3

    float den = 0.f, acc0 = 0.f, acc1 = 0.f;
    for (int jb = start; jb < end; jb += 32) {
        int j = jb + lane;
        int scol = 0;
        float ex = 0.f;
        if (j < end) {
            scol = g_col[j];
            ex = __expf(leaky(g_als2[scol] + ald));
            den += ex;
        }
        int cnt = min(32, end - jb);
        int iters = (cnt + 3) >> 2;          // warp-uniform
        for (int v = 0; v < iters; v++) {
            int su = v * 4 + eg;
            int s = __shfl_sync(0xFFFFFFFFu, scol, su);
            float a = __shfl_sync(0xFFFFFFFFu, ex, su);
            __half2 hh = *(const __half2*)&g_h2h[s * 16 + p * 2];
            float2 f = __half22float2(hh);
            acc0 = fmaf(f.x, a, acc0);
            acc1 = fmaf(f.y, a, acc1);
        }
    }
#pragma unroll
    for (int off = 16; off; off >>= 1) den += __shfl_xor_sync(0xFFFFFFFFu, den, off);
    float rd = 1.0f / den;
    // reduce over edge subgroups (lane bits 3,4)
    acc0 += __shfl_xor_sync(0xFFFFFFFFu, acc0, 8);
    acc1 += __shfl_xor_sync(0xFFFFFFFFu, acc1, 8);
    acc0 += __shfl_xor_sync(0xFFFFFFFFu, acc0, 16);
    acc1 += __shfl_xor_sync(0xFFFFFFFFu, acc1, 16);
    if (lane < 8) {
        float2 o = make_float2(fmaf(acc0, rd, b2[2 * p]),
                               fmaf(acc1, rd, b2[2 * p + 1]));
        *(float2*)&out[(size_t)w * 16 + 2 * p] = o;
    }
}

// ---------------- launch -----------------------------------------------------
extern "C" void kernel_launch(void* const* d_in, const int* in_sizes, int n_in,
                              void* d_out, int out_size) {
    const float* x = (const float*)d_in[0];
    const void* ei = d_in[1];
    const float* W1 = (const float*)d_in[2];
    const float* as1 = (const float*)d_in[3];
    const float* ad1 = (const float*)d_in[4];
    const float* b1 = (const float*)d_in[5];
    const float* W2 = (const float*)d_in[6];
    const float* as2 = (const float*)d_in[7];
    const float* ad2 = (const float*)d_in[8];
    const float* b2 = (const float*)d_in[9];
    float* out = (float*)d_out;

    int N = in_sizes[0] / 128;
    int E = in_sizes[1] / 2;
    if (N > MAXN) N = MAXN;
    if (E > MAXE) E = MAXE;

    static cudaStream_t s2 = nullptr;
    static cudaEvent_t evRoot = nullptr, evG1 = nullptr;
    if (s2 == nullptr) {
        cudaStreamCreateWithFlags(&s2, cudaStreamNonBlocking);
        cudaEventCreateWithFlags(&evRoot, cudaEventDisableTiming);
        cudaEventCreateWithFlags(&evG1, cudaEventDisableTiming);
    }

    // branch: GEMM1 runs parallel to the CSR build
    cudaEventRecord(evRoot, 0);
    cudaStreamWaitEvent(s2, evRoot, 0);
    k_gemm1<<<(N + 127) / 128, 256, 0, s2>>>(x, W1, as1, ad1, N);
    cudaEventRecord(evG1, s2);

    k_probe<<<1, 32>>>((const int*)ei, E);
    k_zero_deg<<<(N + 255) / 256, 256>>>(N);
    k_convert<<<(E + 255) / 256, 256>>>(ei, E, N);
    k_alloc<<<(N + 255) / 256, 256>>>(N);
    k_fill<<<(E + 255) / 256, 256>>>(E);

    cudaStreamWaitEvent(0, evG1, 0);
    k_agg1<<<(N + 7) / 8, 256>>>(b1, N);
    k_gemm2<<<(N + 15) / 16, 256>>>(W2, as2, ad2, N);
    k_agg2<<<(N + 7) / 8, 256>>>(b2, out, N);
}

// round 16
// speedup vs baseline: 1.6079x; 1.0537x over previous
#include <cuda_runtime.h>
#include <cuda_fp16.h>

#define MAXN 100000
#define MAXE 1600000
#define MAXTOT (MAXN + MAXE)
#define NEG_SLOPE 0.2f

// ---------------- scratch ---------------------------------------------------
__device__ __align__(16) __half2 g_h1h[MAXN * 64];   // layer-1 features, fp16
__device__ __align__(16) float g_als1[MAXN * 4];
__device__ __align__(16) float g_ald1[MAXN * 4];
__device__ __align__(16) __half g_h2h[MAXN * 16];    // layer-2 features, fp16
__device__ float g_als2[MAXN];
__device__ float g_ald2[MAXN];
__device__ int g_deg[MAXN];
__device__ int g_rowptr[MAXN];
__device__ int g_rowend[MAXN];
__device__ int g_cursor[MAXN];
__device__ int g_col[MAXTOT];
__device__ int g_src[MAXE];
__device__ int g_dst[MAXE];
__device__ int g_is64;
__device__ int g_total;

// ---------------- f32x2 helpers ---------------------------------------------
__device__ __forceinline__ unsigned long long pack2(float a, float b) {
    unsigned long long r;
    asm("mov.b64 %0, {%1, %2};" : "=l"(r) : "f"(a), "f"(b));
    return r;
}
__device__ __forceinline__ void fma2(unsigned long long& d, unsigned long long a,
                                     unsigned long long b) {
    asm("fma.rn.f32x2 %0, %1, %2, %0;" : "+l"(d) : "l"(a), "l"(b));
}
__device__ __forceinline__ float2 unpack2(unsigned long long v) {
    float2 f;
    asm("mov.b64 {%0, %1}, %2;" : "=f"(f.x), "=f"(f.y) : "l"(v));
    return f;
}

__device__ __forceinline__ float leaky(float e) { return e > 0.f ? e : NEG_SLOPE * e; }

// ---------------- edge-index probe / normalize / count -----------------------
__global__ void k_probe(const int* __restrict__ ei32, int E) {
    if (threadIdx.x == 0 && blockIdx.x == 0) {
        int cnt = E < 64 ? E : 64;
        int zeros = 0;
        for (int i = 0; i < cnt; i++) zeros += (ei32[2 * i + 1] == 0) ? 1 : 0;
        g_is64 = (zeros == cnt) ? 1 : 0;
        g_total = 0;
    }
}

__global__ void k_convert(const void* __restrict__ ei, int E, int N) {
    int e = blockIdx.x * blockDim.x + threadIdx.x;
    if (e >= E) return;
    int s, d;
    if (g_is64) {
        const long long* p = (const long long*)ei;
        s = (int)p[e];
        d = (int)p[E + e];
    } else {
        const int* p = (const int*)ei;
        s = p[e];
        d = p[E + e];
    }
    s = min(max(s, 0), N - 1);
    d = min(max(d, 0), N - 1);
    g_src[e] = s;
    g_dst[e] = d;
    atomicAdd(&g_deg[d], 1);
}

// parallel segment allocator (order-free CSR); resets deg for the next replay
__global__ void k_alloc(int n) {
    int i = blockIdx.x * blockDim.x + threadIdx.x;
    int lane = threadIdx.x & 31;
    int dg = (i < n) ? g_deg[i] : -1;
    int v = dg + 1;                    // deg+1 slots (self loop), 0 if i>=n
    int incl = v;
#pragma unroll
    for (int off = 1; off < 32; off <<= 1) {
        int t = __shfl_up_sync(0xFFFFFFFFu, incl, off);
        if (lane >= off) incl += t;
    }
    int tot = __shfl_sync(0xFFFFFFFFu, incl, 31);
    int base = 0;
    if (lane == 0) base = atomicAdd(&g_total, tot);
    base = __shfl_sync(0xFFFFFFFFu, base, 0);
    int pos = base + incl - v;
    if (i < n) {
        g_rowptr[i] = pos;
        g_rowend[i] = pos + v;
        g_col[pos] = i;                // self loop occupies first slot
        g_cursor[i] = pos + 1;
        g_deg[i] = 0;                  // ready for next replay's convert
    }
}

__global__ void k_fill(int E) {
    int e = blockIdx.x * blockDim.x + threadIdx.x;
    if (e < E) {
        int pos = atomicAdd(&g_cursor[g_dst[e]], 1);
        g_col[pos] = g_src[e];
    }
}

// ---------------- GEMM1: 128x128 tile, 8x8 register blocking, fp16 h1 out ----
__global__ void k_gemm1(const float* __restrict__ x, const float* __restrict__ W,
                        const float* __restrict__ asrc, const float* __restrict__ adst,
                        int n) {
    __shared__ float xs[128 * 33];
    __shared__ float ws[32 * 128];
    int t = threadIdx.x;
    int tx = t & 15, ty = t >> 4;
    int row0 = blockIdx.x * 128;

    unsigned long long acc[8][4];
#pragma unroll
    for (int i = 0; i < 8; i++)
#pragma unroll
        for (int j = 0; j < 4; j++) acc[i][j] = pack2(0.f, 0.f);

    for (int kc = 0; kc < 128; kc += 32) {
        for (int i = t; i < 1024; i += 256) {
            int r = i >> 3, cq = i & 7;
            float4 v = make_float4(0.f, 0.f, 0.f, 0.f);
            if (row0 + r < n)
                v = *(const float4*)&x[(size_t)(row0 + r) * 128 + kc + cq * 4];
            float* p = &xs[r * 33 + cq * 4];
            p[0] = v.x; p[1] = v.y; p[2] = v.z; p[3] = v.w;
        }
        for (int i = t; i < 1024; i += 256)
            *(float4*)&ws[i * 4] = *(const float4*)&W[(size_t)kc * 128 + i * 4];
        __syncthreads();
#pragma unroll 4
        for (int k = 0; k < 32; k++) {
            float4 wa = *(const float4*)&ws[k * 128 + tx * 8];
            float4 wb = *(const float4*)&ws[k * 128 + tx * 8 + 4];
            unsigned long long wp0 = pack2(wa.x, wa.y);
            unsigned long long wp1 = pack2(wa.z, wa.w);
            unsigned long long wp2 = pack2(wb.x, wb.y);
            unsigned long long wp3 = pack2(wb.z, wb.w);
#pragma unroll
            for (int i = 0; i < 8; i++) {
                float xv = xs[(ty * 8 + i) * 33 + k];
                unsigned long long xp = pack2(xv, xv);
                fma2(acc[i][0], xp, wp0);
                fma2(acc[i][1], xp, wp1);
                fma2(acc[i][2], xp, wp2);
                fma2(acc[i][3], xp, wp3);
            }
        }
        __syncthreads();
    }

    int h0 = tx >> 2;
    int base = (tx & 3) * 8;
    float aS[8], aD[8];
#pragma unroll
    for (int j = 0; j < 8; j++) {
        aS[j] = asrc[h0 * 32 + base + j];
        aD[j] = adst[h0 * 32 + base + j];
    }
#pragma unroll
    for (int i = 0; i < 8; i++) {
        int row = row0 + ty * 8 + i;
        float2 p0 = unpack2(acc[i][0]);
        float2 p1 = unpack2(acc[i][1]);
        float2 p2 = unpack2(acc[i][2]);
        float2 p3 = unpack2(acc[i][3]);
        float hv[8] = {p0.x, p0.y, p1.x, p1.y, p2.x, p2.y, p3.x, p3.y};
        if (row < n) {
            __half2 hh[4];
            hh[0] = __floats2half2_rn(hv[0], hv[1]);
            hh[1] = __floats2half2_rn(hv[2], hv[3]);
            hh[2] = __floats2half2_rn(hv[4], hv[5]);
            hh[3] = __floats2half2_rn(hv[6], hv[7]);
            *(float4*)&g_h1h[(size_t)row * 64 + tx * 4] = *(float4*)hh;
        }
        float pS = 0.f, pD = 0.f;
#pragma unroll
        for (int j = 0; j < 8; j++) {
            pS = fmaf(hv[j], aS[j], pS);
            pD = fmaf(hv[j], aD[j], pD);
        }
        pS += __shfl_xor_sync(0xFFFFFFFFu, pS, 1);
        pD += __shfl_xor_sync(0xFFFFFFFFu, pD, 1);
        pS += __shfl_xor_sync(0xFFFFFFFFu, pS, 2);
        pD += __shfl_xor_sync(0xFFFFFFFFu, pD, 2);
        if ((tx & 3) == 0 && row < n) {
            g_als1[row * 4 + h0] = pS;
            g_ald1[row * 4 + h0] = pD;
        }
    }
}

// ---------------- Fused layer-1 aggregation + GEMM2 + layer-2 dots ----------
// Per warp/node: single-pass softmax gather (fp16 h1, front-prefetched), then
// relu(x2+b1) staged in per-warp shared row, in-warp 128x16 GEMM against W2
// (shared), producing g_h2h + g_als2/g_ald2 directly. g_x2 never materializes.
__global__ void k_agg1f(const float* __restrict__ b1, const float* __restrict__ W2,
                        const float* __restrict__ as2, const float* __restrict__ ad2,
                        int n) {
    __shared__ float sW2[128 * 16];            // 8 KB
    __shared__ float sRow[8][132];             // per-warp staged x2 row
    int t = threadIdx.x;
    int wid = t >> 5;
    int lane = t & 31;
    // cooperative W2 load
    for (int i = t; i < 512; i += 256)
        *(float4*)&sW2[i * 4] = *(const float4*)&W2[i * 4];
    __syncthreads();

    int w = (blockIdx.x << 3) + wid;
    if (w >= n) return;
    int start = g_rowptr[w];
    int end = g_rowend[w];
    float4 aldv = *(const float4*)&g_ald1[w * 4];
    int hd = lane & 3;
    float aldd = (hd == 0) ? aldv.x : (hd == 1) ? aldv.y : (hd == 2) ? aldv.z : aldv.w;
    int hg = lane >> 3;
    int c = lane << 2;

    float den = 0.f;
    float a0 = 0.f, a1 = 0.f, a2 = 0.f, a3 = 0.f;

    // front of batch 0
    int j = start + (lane >> 2);
    int scol = 0; float als = 0.f;
    bool valid = (j < end);
    if (valid) { scol = g_col[j]; als = g_als1[scol * 4 + hd]; }

    for (int jb = start; jb < end; jb += 8) {
        float ex = valid ? __expf(leaky(als + aldd)) : 0.f;
        den += ex;
        // prefetch next batch's front
        int jn = jb + 8 + (lane >> 2);
        int nscol = 0; float nals = 0.f;
        bool nvalid = (jn < end);
        if (nvalid) { nscol = g_col[jn]; nals = g_als1[nscol * 4 + hd]; }

        int cnt = min(8, end - jb);
        if (cnt == 8) {
#pragma unroll
            for (int u = 0; u < 8; u++) {
                int s = __shfl_sync(0xFFFFFFFFu, scol, u * 4);
                float a = __shfl_sync(0xFFFFFFFFu, ex, u * 4 + hg);
                uint2 raw = *(const uint2*)&g_h1h[(size_t)s * 64 + lane * 2];
                float2 f0 = __half22float2(*(__half2*)&raw.x);
                float2 f1 = __half22float2(*(__half2*)&raw.y);
                a0 = fmaf(f0.x, a, a0);
                a1 = fmaf(f0.y, a, a1);
                a2 = fmaf(f1.x, a, a2);
                a3 = fmaf(f1.y, a, a3);
            }
        } else {
            for (int u = 0; u < cnt; u++) {
                int s = __shfl_sync(0xFFFFFFFFu, scol, u * 4);
                float a = __shfl_sync(0xFFFFFFFFu, ex, u * 4 + hg);
                uint2 raw = *(const uint2*)&g_h1h[(size_t)s * 64 + lane * 2];
                float2 f0 = __half22float2(*(__half2*)&raw.x);
                float2 f1 = __half22float2(*(__half2*)&raw.y);
                a0 = fmaf(f0.x, a, a0);
                a1 = fmaf(f0.y, a, a1);
                a2 = fmaf(f1.x, a, a2);
                a3 = fmaf(f1.y, a, a3);
            }
        }
        scol = nscol; als = nals; valid = nvalid;
    }
    den += __shfl_xor_sync(0xFFFFFFFFu, den, 4);
    den += __shfl_xor_sync(0xFFFFFFFFu, den, 8);
    den += __shfl_xor_sync(0xFFFFFFFFu, den, 16);
    float rd = 1.0f / den;
    float rdg = __shfl_sync(0xFFFFFFFFu, rd, hg);
    float4 bb = *(const float4*)&b1[c];
    float* row = sRow[wid];
    row[c + 0] = fmaxf(fmaf(a0, rdg, bb.x), 0.f);
    row[c + 1] = fmaxf(fmaf(a1, rdg, bb.y), 0.f);
    row[c + 2] = fmaxf(fmaf(a2, rdg, bb.z), 0.f);
    row[c + 3] = fmaxf(fmaf(a3, rdg, bb.w), 0.f);
    __syncwarp();

    // in-warp GEMM: h2[o] = sum_k row[k] * W2[k][o]; lanes>=16 duplicate o&15
    int o = lane & 15;
    float h2 = 0.f;
#pragma unroll 8
    for (int k = 0; k < 128; k += 4) {
        float4 r4 = *(const float4*)&row[k];
        h2 = fmaf(r4.x, sW2[(k + 0) * 16 + o], h2);
        h2 = fmaf(r4.y, sW2[(k + 1) * 16 + o], h2);
        h2 = fmaf(r4.z, sW2[(k + 2) * 16 + o], h2);
        h2 = fmaf(r4.w, sW2[(k + 3) * 16 + o], h2);
    }
    if (lane < 16) g_h2h[w * 16 + o] = __float2half_rn(h2);
    // layer-2 attention dots (mask duplicate lanes)
    float pS = (lane < 16) ? h2 * as2[o] : 0.f;
    float pD = (lane < 16) ? h2 * ad2[o] : 0.f;
#pragma unroll
    for (int off = 16; off; off >>= 1) {
        pS += __shfl_xor_sync(0xFFFFFFFFu, pS, off);
        pD += __shfl_xor_sync(0xFFFFFFFFu, pD, off);
    }
    if (lane == 0) {
        g_als2[w] = pS;
        g_ald2[w] = pD;
    }
}

// ---------------- Layer-2 aggregation: single-pass, fp16, bounded MLP-4 ------
__global__ void k_agg2(const float* __restrict__ b2, float* __restrict__ out, int n) {
    int w = (blockIdx.x * blockDim.x + threadIdx.x) >> 5;
    int lane = threadIdx.x & 31;
    if (w >= n) return;
    int start = g_rowptr[w];
    int end = g_rowend[w];
    float ald = g_ald2[w];
    int p = lane & 7;        // col pair index: cols 2p, 2p+1
    int eg = lane >> 3;      // edge subgroup 0..3

    float den = 0.f, acc0 = 0.f, acc1 = 0.f;
    for (int jb = start; jb < end; jb += 32) {
        int j = jb + lane;
        int scol = 0;
        float ex = 0.f;
        if (j < end) {
            scol = g_col[j];
            ex = __expf(leaky(g_als2[scol] + ald));
            den += ex;
        }
        int cnt = min(32, end - jb);
        int iters = (cnt + 3) >> 2;          // warp-uniform
        for (int v = 0; v < iters; v++) {
            int su = v * 4 + eg;
            int s = __shfl_sync(0xFFFFFFFFu, scol, su);
            float a = __shfl_sync(0xFFFFFFFFu, ex, su);
            __half2 hh = *(const __half2*)&g_h2h[s * 16 + p * 2];
            float2 f = __half22float2(hh);
            acc0 = fmaf(f.x, a, acc0);
            acc1 = fmaf(f.y, a, acc1);
        }
    }
#pragma unroll
    for (int off = 16; off; off >>= 1) den += __shfl_xor_sync(0xFFFFFFFFu, den, off);
    float rd = 1.0f / den;
    acc0 += __shfl_xor_sync(0xFFFFFFFFu, acc0, 8);
    acc1 += __shfl_xor_sync(0xFFFFFFFFu, acc1, 8);
    acc0 += __shfl_xor_sync(0xFFFFFFFFu, acc0, 16);
    acc1 += __shfl_xor_sync(0xFFFFFFFFu, acc1, 16);
    if (lane < 8) {
        float2 o = make_float2(fmaf(acc0, rd, b2[2 * p]),
                               fmaf(acc1, rd, b2[2 * p + 1]));
        *(float2*)&out[(size_t)w * 16 + 2 * p] = o;
    }
}

// ---------------- launch -----------------------------------------------------
extern "C" void kernel_launch(void* const* d_in, const int* in_sizes, int n_in,
                              void* d_out, int out_size) {
    const float* x = (const float*)d_in[0];
    const void* ei = d_in[1];
    const float* W1 = (const float*)d_in[2];
    const float* as1 = (const float*)d_in[3];
    const float* ad1 = (const float*)d_in[4];
    const float* b1 = (const float*)d_in[5];
    const float* W2 = (const float*)d_in[6];
    const float* as2 = (const float*)d_in[7];
    const float* ad2 = (const float*)d_in[8];
    const float* b2 = (const float*)d_in[9];
    float* out = (float*)d_out;

    int N = in_sizes[0] / 128;
    int E = in_sizes[1] / 2;
    if (N > MAXN) N = MAXN;
    if (E > MAXE) E = MAXE;

    static cudaStream_t s2 = nullptr;
    static cudaEvent_t evRoot = nullptr, evG1 = nullptr;
    if (s2 == nullptr) {
        cudaStreamCreateWithFlags(&s2, cudaStreamNonBlocking);
        cudaEventCreateWithFlags(&evRoot, cudaEventDisableTiming);
        cudaEventCreateWithFlags(&evG1, cudaEventDisableTiming);
    }

    // branch: GEMM1 runs parallel to the CSR build
    cudaEventRecord(evRoot, 0);
    cudaStreamWaitEvent(s2, evRoot, 0);
    k_gemm1<<<(N + 127) / 128, 256, 0, s2>>>(x, W1, as1, ad1, N);
    cudaEventRecord(evG1, s2);

    k_probe<<<1, 32>>>((const int*)ei, E);
    k_convert<<<(E + 255) / 256, 256>>>(ei, E, N);
    k_alloc<<<(N + 255) / 256, 256>>>(N);
    k_fill<<<(E + 255) / 256, 256>>>(E);

    cudaStreamWaitEvent(0, evG1, 0);
    k_agg1f<<<(N + 7) / 8, 256>>>(b1, W2, as2, ad2, N);
    k_agg2<<<(N + 7) / 8, 256>>>(b2, out, N);
}

// round 17
// speedup vs baseline: 1.6496x; 1.0259x over previous
#include <cuda_runtime.h>
#include <cuda_fp16.h>

#define MAXN 100000
#define MAXE 1600000
#define MAXTOT (MAXN + MAXE)
#define NEG_SLOPE 0.2f

// ---------------- scratch ---------------------------------------------------
__device__ __align__(16) __half2 g_h1h[MAXN * 64];   // layer-1 features, fp16
__device__ __align__(16) float g_als1[MAXN * 4];
__device__ __align__(16) float g_ald1[MAXN * 4];
__device__ __align__(16) __half g_h2h[MAXN * 16];    // layer-2 features, fp16
__device__ float g_als2[MAXN];
__device__ float g_ald2[MAXN];
__device__ int g_deg[MAXN];
__device__ int g_rowptr[MAXN];
__device__ int g_rowend[MAXN];
__device__ int g_cursor[MAXN];
__device__ int g_col[MAXTOT];
__device__ int g_src[MAXE];
__device__ int g_dst[MAXE];
__device__ int g_is64;
__device__ int g_total;

// ---------------- f32x2 helpers ---------------------------------------------
__device__ __forceinline__ unsigned long long pack2(float a, float b) {
    unsigned long long r;
    asm("mov.b64 %0, {%1, %2};" : "=l"(r) : "f"(a), "f"(b));
    return r;
}
__device__ __forceinline__ void fma2(unsigned long long& d, unsigned long long a,
                                     unsigned long long b) {
    asm("fma.rn.f32x2 %0, %1, %2, %0;" : "+l"(d) : "l"(a), "l"(b));
}
__device__ __forceinline__ float2 unpack2(unsigned long long v) {
    float2 f;
    asm("mov.b64 {%0, %1}, %2;" : "=f"(f.x), "=f"(f.y) : "l"(v));
    return f;
}

__device__ __forceinline__ float leaky(float e) { return e > 0.f ? e : NEG_SLOPE * e; }

// ---------------- edge-index probe / normalize / count -----------------------
__global__ void k_probe(const int* __restrict__ ei32, int E) {
    if (threadIdx.x == 0 && blockIdx.x == 0) {
        int cnt = E < 64 ? E : 64;
        int zeros = 0;
        for (int i = 0; i < cnt; i++) zeros += (ei32[2 * i + 1] == 0) ? 1 : 0;
        g_is64 = (zeros == cnt) ? 1 : 0;
        g_total = 0;
    }
}

__global__ void k_convert(const void* __restrict__ ei, int E, int N) {
    int e = blockIdx.x * blockDim.x + threadIdx.x;
    if (e >= E) return;
    int s, d;
    if (g_is64) {
        const long long* p = (const long long*)ei;
        s = (int)p[e];
        d = (int)p[E + e];
    } else {
        const int* p = (const int*)ei;
        s = p[e];
        d = p[E + e];
    }
    s = min(max(s, 0), N - 1);
    d = min(max(d, 0), N - 1);
    g_src[e] = s;
    g_dst[e] = d;
    atomicAdd(&g_deg[d], 1);
}

// parallel segment allocator (order-free CSR); resets deg for the next replay
__global__ void k_alloc(int n) {
    int i = blockIdx.x * blockDim.x + threadIdx.x;
    int lane = threadIdx.x & 31;
    int dg = (i < n) ? g_deg[i] : -1;
    int v = dg + 1;
    int incl = v;
#pragma unroll
    for (int off = 1; off < 32; off <<= 1) {
        int t = __shfl_up_sync(0xFFFFFFFFu, incl, off);
        if (lane >= off) incl += t;
    }
    int tot = __shfl_sync(0xFFFFFFFFu, incl, 31);
    int base = 0;
    if (lane == 0) base = atomicAdd(&g_total, tot);
    base = __shfl_sync(0xFFFFFFFFu, base, 0);
    int pos = base + incl - v;
    if (i < n) {
        g_rowptr[i] = pos;
        g_rowend[i] = pos + v;
        g_col[pos] = i;                // self loop occupies first slot
        g_cursor[i] = pos + 1;
        g_deg[i] = 0;                  // ready for next replay's convert
    }
}

__global__ void k_fill(int E) {
    int e = blockIdx.x * blockDim.x + threadIdx.x;
    if (e < E) {
        int pos = atomicAdd(&g_cursor[g_dst[e]], 1);
        g_col[pos] = g_src[e];
    }
}

// ---------------- GEMM1: 128x128 tile, 8x8 register blocking, fp16 h1 out ----
__global__ void k_gemm1(const float* __restrict__ x, const float* __restrict__ W,
                        const float* __restrict__ asrc, const float* __restrict__ adst,
                        int n) {
    __shared__ float xs[128 * 33];
    __shared__ float ws[32 * 128];
    int t = threadIdx.x;
    int tx = t & 15, ty = t >> 4;
    int row0 = blockIdx.x * 128;

    unsigned long long acc[8][4];
#pragma unroll
    for (int i = 0; i < 8; i++)
#pragma unroll
        for (int j = 0; j < 4; j++) acc[i][j] = pack2(0.f, 0.f);

    for (int kc = 0; kc < 128; kc += 32) {
        for (int i = t; i < 1024; i += 256) {
            int r = i >> 3, cq = i & 7;
            float4 v = make_float4(0.f, 0.f, 0.f, 0.f);
            if (row0 + r < n)
                v = *(const float4*)&x[(size_t)(row0 + r) * 128 + kc + cq * 4];
            float* p = &xs[r * 33 + cq * 4];
            p[0] = v.x; p[1] = v.y; p[2] = v.z; p[3] = v.w;
        }
        for (int i = t; i < 1024; i += 256)
            *(float4*)&ws[i * 4] = *(const float4*)&W[(size_t)kc * 128 + i * 4];
        __syncthreads();
#pragma unroll 4
        for (int k = 0; k < 32; k++) {
            float4 wa = *(const float4*)&ws[k * 128 + tx * 8];
            float4 wb = *(const float4*)&ws[k * 128 + tx * 8 + 4];
            unsigned long long wp0 = pack2(wa.x, wa.y);
            unsigned long long wp1 = pack2(wa.z, wa.w);
            unsigned long long wp2 = pack2(wb.x, wb.y);
            unsigned long long wp3 = pack2(wb.z, wb.w);
#pragma unroll
            for (int i = 0; i < 8; i++) {
                float xv = xs[(ty * 8 + i) * 33 + k];
                unsigned long long xp = pack2(xv, xv);
                fma2(acc[i][0], xp, wp0);
                fma2(acc[i][1], xp, wp1);
                fma2(acc[i][2], xp, wp2);
                fma2(acc[i][3], xp, wp3);
            }
        }
        __syncthreads();
    }

    int h0 = tx >> 2;
    int base = (tx & 3) * 8;
    float aS[8], aD[8];
#pragma unroll
    for (int j = 0; j < 8; j++) {
        aS[j] = asrc[h0 * 32 + base + j];
        aD[j] = adst[h0 * 32 + base + j];
    }
#pragma unroll
    for (int i = 0; i < 8; i++) {
        int row = row0 + ty * 8 + i;
        float2 p0 = unpack2(acc[i][0]);
        float2 p1 = unpack2(acc[i][1]);
        float2 p2 = unpack2(acc[i][2]);
        float2 p3 = unpack2(acc[i][3]);
        float hv[8] = {p0.x, p0.y, p1.x, p1.y, p2.x, p2.y, p3.x, p3.y};
        if (row < n) {
            __half2 hh[4];
            hh[0] = __floats2half2_rn(hv[0], hv[1]);
            hh[1] = __floats2half2_rn(hv[2], hv[3]);
            hh[2] = __floats2half2_rn(hv[4], hv[5]);
            hh[3] = __floats2half2_rn(hv[6], hv[7]);
            *(float4*)&g_h1h[(size_t)row * 64 + tx * 4] = *(float4*)hh;
        }
        float pS = 0.f, pD = 0.f;
#pragma unroll
        for (int j = 0; j < 8; j++) {
            pS = fmaf(hv[j], aS[j], pS);
            pD = fmaf(hv[j], aD[j], pD);
        }
        pS += __shfl_xor_sync(0xFFFFFFFFu, pS, 1);
        pD += __shfl_xor_sync(0xFFFFFFFFu, pD, 1);
        pS += __shfl_xor_sync(0xFFFFFFFFu, pS, 2);
        pD += __shfl_xor_sync(0xFFFFFFFFu, pD, 2);
        if ((tx & 3) == 0 && row < n) {
            g_als1[row * 4 + h0] = pS;
            g_ald1[row * 4 + h0] = pD;
        }
    }
}

// ---------------- Fused layer-1 aggregation + GEMM2 + layer-2 dots ----------
// Shuffle-free gather: scol via warp-broadcast load, per-lane ex for its own
// output head (den accumulates redundantly per lane -> no reductions at all).
__global__ void k_agg1f(const float* __restrict__ b1, const float* __restrict__ W2,
                        const float* __restrict__ as2, const float* __restrict__ ad2,
                        int n) {
    __shared__ float sW2[128 * 16];            // 8 KB
    __shared__ float sRow[8][132];             // per-warp staged x2 row
    int t = threadIdx.x;
    int wid = t >> 5;
    int lane = t & 31;
    for (int i = t; i < 512; i += 256)
        *(float4*)&sW2[i * 4] = *(const float4*)&W2[i * 4];
    __syncthreads();

    int w = (blockIdx.x << 3) + wid;
    if (w >= n) return;
    int start = g_rowptr[w];
    int end = g_rowend[w];
    int hg = lane >> 3;                       // this lane's output head
    float aldg = g_ald1[w * 4 + hg];          // 4 addrs/warp
    int c = lane << 2;

    float den = 0.f;
    float a0 = 0.f, a1 = 0.f, a2 = 0.f, a3 = 0.f;

    int j = start;
    for (; j + 8 <= end; j += 8) {
#pragma unroll
        for (int u = 0; u < 8; u++) {
            int s = __ldg(&g_col[j + u]);                 // uniform -> broadcast
            float als = g_als1[s * 4 + hg];               // 1 sector/warp
            float ex = __expf(leaky(als + aldg));
            den += ex;
            uint2 raw = *(const uint2*)&g_h1h[(size_t)s * 64 + lane * 2];
            float2 f0 = __half22float2(*(__half2*)&raw.x);
            float2 f1 = __half22float2(*(__half2*)&raw.y);
            a0 = fmaf(f0.x, ex, a0);
            a1 = fmaf(f0.y, ex, a1);
            a2 = fmaf(f1.x, ex, a2);
            a3 = fmaf(f1.y, ex, a3);
        }
    }
    for (; j < end; j++) {
        int s = __ldg(&g_col[j]);
        float als = g_als1[s * 4 + hg];
        float ex = __expf(leaky(als + aldg));
        den += ex;
        uint2 raw = *(const uint2*)&g_h1h[(size_t)s * 64 + lane * 2];
        float2 f0 = __half22float2(*(__half2*)&raw.x);
        float2 f1 = __half22float2(*(__half2*)&raw.y);
        a0 = fmaf(f0.x, ex, a0);
        a1 = fmaf(f0.y, ex, a1);
        a2 = fmaf(f1.x, ex, a2);
        a3 = fmaf(f1.y, ex, a3);
    }
    float rd = 1.0f / den;                    // den already per-head, per-lane
    float4 bb = *(const float4*)&b1[c];
    float* row = sRow[wid];
    row[c + 0] = fmaxf(fmaf(a0, rd, bb.x), 0.f);
    row[c + 1] = fmaxf(fmaf(a1, rd, bb.y), 0.f);
    row[c + 2] = fmaxf(fmaf(a2, rd, bb.z), 0.f);
    row[c + 3] = fmaxf(fmaf(a3, rd, bb.w), 0.f);
    __syncwarp();

    // in-warp GEMM: h2[o] = sum_k row[k] * W2[k][o]; lanes>=16 duplicate o&15
    int o = lane & 15;
    float h2 = 0.f;
#pragma unroll 8
    for (int k = 0; k < 128; k += 4) {
        float4 r4 = *(const float4*)&row[k];
        h2 = fmaf(r4.x, sW2[(k + 0) * 16 + o], h2);
        h2 = fmaf(r4.y, sW2[(k + 1) * 16 + o], h2);
        h2 = fmaf(r4.z, sW2[(k + 2) * 16 + o], h2);
        h2 = fmaf(r4.w, sW2[(k + 3) * 16 + o], h2);
    }
    if (lane < 16) g_h2h[w * 16 + o] = __float2half_rn(h2);
    float pS = (lane < 16) ? h2 * as2[o] : 0.f;
    float pD = (lane < 16) ? h2 * ad2[o] : 0.f;
#pragma unroll
    for (int off = 16; off; off >>= 1) {
        pS += __shfl_xor_sync(0xFFFFFFFFu, pS, off);
        pD += __shfl_xor_sync(0xFFFFFFFFu, pD, off);
    }
    if (lane == 0) {
        g_als2[w] = pS;
        g_ald2[w] = pD;
    }
}

// ---------------- Layer-2 aggregation: single-pass, fp16, bounded MLP-4 ------
__global__ void k_agg2(const float* __restrict__ b2, float* __restrict__ out, int n) {
    int w = (blockIdx.x * blockDim.x + threadIdx.x) >> 5;
    int lane = threadIdx.x & 31;
    if (w >= n) return;
    int start = g_rowptr[w];
    int end = g_rowend[w];
    float ald = g_ald2[w];
    int p = lane & 7;
    int eg = lane >> 3;

    float den = 0.f, acc0 = 0.f, acc1 = 0.f;
    for (int jb = start; jb < end; jb += 32) {
        int j = jb + lane;
        int scol = 0;
        float ex = 0.f;
        if (j < end) {
            scol = g_col[j];
            ex = __expf(leaky(g_als2[scol] + ald));
            den += ex;
        }
        int cnt = min(32, end - jb);
        int iters = (cnt + 3) >> 2;
        for (int v = 0; v < iters; v++) {
            int su = v * 4 + eg;
            int s = __shfl_sync(0xFFFFFFFFu, scol, su);
            float a = __shfl_sync(0xFFFFFFFFu, ex, su);
            __half2 hh = *(const __half2*)&g_h2h[s * 16 + p * 2];
            float2 f = __half22float2(hh);
            acc0 = fmaf(f.x, a, acc0);
            acc1 = fmaf(f.y, a, acc1);
        }
    }
#pragma unroll
    for (int off = 16; off; off >>= 1) den += __shfl_xor_sync(0xFFFFFFFFu, den, off);
    float rd = 1.0f / den;
    acc0 += __shfl_xor_sync(0xFFFFFFFFu, acc0, 8);
    acc1 += __shfl_xor_sync(0xFFFFFFFFu, acc1, 8);
    acc0 += __shfl_xor_sync(0xFFFFFFFFu, acc0, 16);
    acc1 += __shfl_xor_sync(0xFFFFFFFFu, acc1, 16);
    if (lane < 8) {
        float2 o = make_float2(fmaf(acc0, rd, b2[2 * p]),
                               fmaf(acc1, rd, b2[2 * p + 1]));
        *(float2*)&out[(size_t)w * 16 + 2 * p] = o;
    }
}

// ---------------- launch -----------------------------------------------------
extern "C" void kernel_launch(void* const* d_in, const int* in_sizes, int n_in,
                              void* d_out, int out_size) {
    const float* x = (const float*)d_in[0];
    const void* ei = d_in[1];
    const float* W1 = (const float*)d_in[2];
    const float* as1 = (const float*)d_in[3];
    const float* ad1 = (const float*)d_in[4];
    const float* b1 = (const float*)d_in[5];
    const float* W2 = (const float*)d_in[6];
    const float* as2 = (const float*)d_in[7];
    const float* ad2 = (const float*)d_in[8];
    const float* b2 = (const float*)d_in[9];
    float* out = (float*)d_out;

    int N = in_sizes[0] / 128;
    int E = in_sizes[1] / 2;
    if (N > MAXN) N = MAXN;
    if (E > MAXE) E = MAXE;

    static cudaStream_t s2 = nullptr;
    static cudaEvent_t evRoot = nullptr, evG1 = nullptr;
    if (s2 == nullptr) {
        cudaStreamCreateWithFlags(&s2, cudaStreamNonBlocking);
        cudaEventCreateWithFlags(&evRoot, cudaEventDisableTiming);
        cudaEventCreateWithFlags(&evG1, cudaEventDisableTiming);
    }

    // branch: GEMM1 runs parallel to the CSR build
    cudaEventRecord(evRoot, 0);
    cudaStreamWaitEvent(s2, evRoot, 0);
    k_gemm1<<<(N + 127) / 128, 256, 0, s2>>>(x, W1, as1, ad1, N);
    cudaEventRecord(evG1, s2);

    k_probe<<<1, 32>>>((const int*)ei, E);
    k_convert<<<(E + 255) / 256, 256>>>(ei, E, N);
    k_alloc<<<(N + 255) / 256, 256>>>(N);
    k_fill<<<(E + 255) / 256, 256>>>(E);

    cudaStreamWaitEvent(0, evG1, 0);
    k_agg1f<<<(N + 7) / 8, 256>>>(b1, W2, as2, ad2, N);
    k_agg2<<<(N + 7) / 8, 256>>>(b2, out, N);
}